// round 1
// baseline (speedup 1.0000x reference)
#include <cuda_runtime.h>
#include <cuda_bf16.h>

#define B_    4
#define SEQ_  4096
#define D_    64
#define V_    512
#define BS_   32
#define CHUNK 8

// Scratch (device globals — no allocation allowed)
__device__ float g_qT[(size_t)B_ * D_ * SEQ_];            // [b][d][m]
__device__ float g_eT[(size_t)B_ * D_ * V_];              // [b][d][v]
__device__ float g_scores[(size_t)B_ * SEQ_ * V_];        // [b][m][v]

// ---------------------------------------------------------------------------
// Transpose [R][C] -> [C][R] per batch (32x32 smem tiles), all dims %32 == 0
// ---------------------------------------------------------------------------
__device__ __forceinline__ void transpose_body(const float* __restrict__ in,
                                               float* __restrict__ out,
                                               int R, int C) {
    __shared__ float tile[32][33];
    const float* inb = in + (size_t)blockIdx.z * R * C;
    float* outb = out + (size_t)blockIdx.z * R * C;
    int c0 = blockIdx.x * 32;
    int r0 = blockIdx.y * 32;
#pragma unroll
    for (int dy = 0; dy < 32; dy += 8)
        tile[threadIdx.y + dy][threadIdx.x] =
            inb[(size_t)(r0 + threadIdx.y + dy) * C + c0 + threadIdx.x];
    __syncthreads();
#pragma unroll
    for (int dy = 0; dy < 32; dy += 8)
        outb[(size_t)(c0 + threadIdx.y + dy) * R + r0 + threadIdx.x] =
            tile[threadIdx.x][threadIdx.y + dy];
}

__global__ void transpose_q_kernel(const float* __restrict__ q) {
    transpose_body(q, g_qT, SEQ_, D_);
}
__global__ void transpose_e_kernel(const float* __restrict__ emb) {
    transpose_body(emb, g_eT, V_, D_);
}

// ---------------------------------------------------------------------------
// GEMM: scores[b][m][v] = sum_k qT[b][k][m] * eT[b][k][v]
// CTA tile 128(M) x 128(V), K staged in two 32-deep smem phases (32 KB smem).
// 256 threads, 8x8 micro-tile per thread.
// ---------------------------------------------------------------------------
__global__ __launch_bounds__(256) void gemm_kernel() {
    __shared__ float qs[32][128];
    __shared__ float es[32][128];

    const int b = blockIdx.z;
    const int mBase = blockIdx.x * 128;
    const int vBase = blockIdx.y * 128;
    const int tid = threadIdx.x;
    const int tx = tid & 15;   // v direction (16)
    const int ty = tid >> 4;   // m direction (16)

    const float* __restrict__ qTb = g_qT + (size_t)b * D_ * SEQ_;
    const float* __restrict__ eTb = g_eT + (size_t)b * D_ * V_;

    float acc[8][8];
#pragma unroll
    for (int i = 0; i < 8; ++i)
#pragma unroll
        for (int j = 0; j < 8; ++j) acc[i][j] = 0.0f;

    const int f  = tid & 31;   // float4 column within 128-wide tile row
    const int kr = tid >> 5;   // 0..7

#pragma unroll
    for (int kp = 0; kp < 2; ++kp) {
        // Load 32 k-rows of q tile and emb tile (coalesced, conflict-free)
#pragma unroll
        for (int t = 0; t < 4; ++t) {
            int k = kr + t * 8;
            *(float4*)&qs[k][f * 4] =
                *(const float4*)&qTb[(size_t)(kp * 32 + k) * SEQ_ + mBase + f * 4];
            *(float4*)&es[k][f * 4] =
                *(const float4*)&eTb[(size_t)(kp * 32 + k) * V_ + vBase + f * 4];
        }
        __syncthreads();

#pragma unroll 8
        for (int k = 0; k < 32; ++k) {
            float qv[8], ev[8];
            *(float4*)&qv[0] = *(const float4*)&qs[k][ty * 8];
            *(float4*)&qv[4] = *(const float4*)&qs[k][ty * 8 + 4];
            *(float4*)&ev[0] = *(const float4*)&es[k][tx * 8];
            *(float4*)&ev[4] = *(const float4*)&es[k][tx * 8 + 4];
#pragma unroll
            for (int i = 0; i < 8; ++i)
#pragma unroll
                for (int j = 0; j < 8; ++j)
                    acc[i][j] = fmaf(qv[i], ev[j], acc[i][j]);
        }
        __syncthreads();
    }

    // Write back (float4 x2 per row)
#pragma unroll
    for (int i = 0; i < 8; ++i) {
        float* dst = g_scores + ((size_t)b * SEQ_ + mBase + ty * 8 + i) * V_
                     + vBase + tx * 8;
        float4 o0 = make_float4(acc[i][0], acc[i][1], acc[i][2], acc[i][3]);
        float4 o1 = make_float4(acc[i][4], acc[i][5], acc[i][6], acc[i][7]);
        *(float4*)dst = o0;
        *(float4*)(dst + 4) = o1;
    }
}

// ---------------------------------------------------------------------------
// Gather: out[p][i][j] = scores[b, rb*32 + i, info[p][i][j]]
// One CTA = CHUNK consecutive panels. Panels sharing (b, rb) are contiguous in
// p (tril_indices order), so the 32 score rows they need are staged in smem
// once per run. Staged as two 16-row halves (32 KB) to stay under the static
// smem limit; h is the outer loop so each half is still loaded once per run.
// ---------------------------------------------------------------------------
__global__ __launch_bounds__(256) void gather_kernel(
    const int* __restrict__ info,
    const int* __restrict__ idxs_batch,
    const int* __restrict__ idxs_row,
    float* __restrict__ out,
    int P) {
    __shared__ float s[16 * V_];   // 32 KB: 16 score rows

    const int p0 = blockIdx.x * CHUNK;
    const int pend = min(p0 + CHUNK, P);
    if (p0 >= P) return;

#pragma unroll
    for (int h = 0; h < 2; ++h) {
        int cached = -1;
        for (int p = p0; p < pend; ++p) {
            const int b  = __ldg(&idxs_batch[p]);
            const int rb = __ldg(&idxs_row[p]);
            const int key = (b << 8) | rb;
            if (key != cached) {
                __syncthreads();   // previous panel's gathers done
                const float4* __restrict__ src = (const float4*)(
                    g_scores + ((size_t)b * SEQ_ + rb * BS_ + h * 16) * V_);
                float4* dst = (float4*)s;
#pragma unroll
                for (int t = 0; t < 8; ++t)
                    dst[threadIdx.x + t * 256] = src[threadIdx.x + t * 256];
                cached = key;
                __syncthreads();
            }
            // 512 elements in this half: 2 per thread
            const int2* __restrict__ ip =
                (const int2*)(info + (size_t)p * 1024 + h * 512);
            float2* op = (float2*)(out + (size_t)p * 1024 + h * 512);
            int2 idx = ip[threadIdx.x];
            const float* srow = s + (threadIdx.x >> 4) * V_;  // i_local = tid*2/32
            float2 o;
            o.x = srow[idx.x];
            o.y = srow[idx.y];
            op[threadIdx.x] = o;
        }
    }
}

// ---------------------------------------------------------------------------
extern "C" void kernel_launch(void* const* d_in, const int* in_sizes, int n_in,
                              void* d_out, int out_size) {
    const float* q    = (const float*)d_in[0];
    const float* emb  = (const float*)d_in[1];
    const int*   info = (const int*)d_in[2];
    const int*   idxb = (const int*)d_in[3];
    const int*   idxr = (const int*)d_in[4];
    float* out = (float*)d_out;
    const int P = in_sizes[3];

    dim3 tb(32, 8);
    transpose_q_kernel<<<dim3(D_ / 32, SEQ_ / 32, B_), tb>>>(q);
    transpose_e_kernel<<<dim3(D_ / 32, V_ / 32, B_), tb>>>(emb);

    gemm_kernel<<<dim3(SEQ_ / 128, V_ / 128, B_), 256>>>();

    gather_kernel<<<(P + CHUNK - 1) / CHUNK, 256>>>(info, idxb, idxr, out, P);
}

// round 2
// speedup vs baseline: 1.1063x; 1.1063x over previous
#include <cuda_runtime.h>
#include <cuda_bf16.h>

#define B_    4
#define SEQ_  4096
#define D_    64
#define V_    512
#define BS_   32
#define CHUNK 16

// Scratch (device globals — no allocation allowed)
__device__ float g_qT[(size_t)B_ * D_ * SEQ_];            // [b][d][m]
__device__ float g_eT[(size_t)B_ * D_ * V_];              // [b][d][v]
__device__ float g_scores[(size_t)B_ * SEQ_ * V_];        // [b][m][v]

// ---------------------------------------------------------------------------
// Transpose [R][C] -> [C][R] per batch (32x32 smem tiles), all dims %32 == 0
// ---------------------------------------------------------------------------
__device__ __forceinline__ void transpose_body(const float* __restrict__ in,
                                               float* __restrict__ out,
                                               int R, int C) {
    __shared__ float tile[32][33];
    const float* inb = in + (size_t)blockIdx.z * R * C;
    float* outb = out + (size_t)blockIdx.z * R * C;
    int c0 = blockIdx.x * 32;
    int r0 = blockIdx.y * 32;
#pragma unroll
    for (int dy = 0; dy < 32; dy += 8)
        tile[threadIdx.y + dy][threadIdx.x] =
            inb[(size_t)(r0 + threadIdx.y + dy) * C + c0 + threadIdx.x];
    __syncthreads();
#pragma unroll
    for (int dy = 0; dy < 32; dy += 8)
        outb[(size_t)(c0 + threadIdx.y + dy) * R + r0 + threadIdx.x] =
            tile[threadIdx.x][threadIdx.y + dy];
}

__global__ void transpose_q_kernel(const float* __restrict__ q) {
    transpose_body(q, g_qT, SEQ_, D_);
}
__global__ void transpose_e_kernel(const float* __restrict__ emb) {
    transpose_body(emb, g_eT, V_, D_);
}

// ---------------------------------------------------------------------------
// GEMM: scores[b][m][v] = sum_k qT[b][k][m] * eT[b][k][v]
// CTA tile 128(M) x 128(V), K staged in two 32-deep smem phases (32 KB smem).
// 256 threads, 8x8 micro-tile per thread.
// ---------------------------------------------------------------------------
__global__ __launch_bounds__(256) void gemm_kernel() {
    __shared__ float qs[32][128];
    __shared__ float es[32][128];

    const int b = blockIdx.z;
    const int mBase = blockIdx.x * 128;
    const int vBase = blockIdx.y * 128;
    const int tid = threadIdx.x;
    const int tx = tid & 15;   // v direction (16)
    const int ty = tid >> 4;   // m direction (16)

    const float* __restrict__ qTb = g_qT + (size_t)b * D_ * SEQ_;
    const float* __restrict__ eTb = g_eT + (size_t)b * D_ * V_;

    float acc[8][8];
#pragma unroll
    for (int i = 0; i < 8; ++i)
#pragma unroll
        for (int j = 0; j < 8; ++j) acc[i][j] = 0.0f;

    const int f  = tid & 31;   // float4 column within 128-wide tile row
    const int kr = tid >> 5;   // 0..7

#pragma unroll
    for (int kp = 0; kp < 2; ++kp) {
        // Load 32 k-rows of q tile and emb tile (coalesced, conflict-free)
#pragma unroll
        for (int t = 0; t < 4; ++t) {
            int k = kr + t * 8;
            *(float4*)&qs[k][f * 4] =
                *(const float4*)&qTb[(size_t)(kp * 32 + k) * SEQ_ + mBase + f * 4];
            *(float4*)&es[k][f * 4] =
                *(const float4*)&eTb[(size_t)(kp * 32 + k) * V_ + vBase + f * 4];
        }
        __syncthreads();

#pragma unroll 8
        for (int k = 0; k < 32; ++k) {
            float qv[8], ev[8];
            *(float4*)&qv[0] = *(const float4*)&qs[k][ty * 8];
            *(float4*)&qv[4] = *(const float4*)&qs[k][ty * 8 + 4];
            *(float4*)&ev[0] = *(const float4*)&es[k][tx * 8];
            *(float4*)&ev[4] = *(const float4*)&es[k][tx * 8 + 4];
#pragma unroll
            for (int i = 0; i < 8; ++i)
#pragma unroll
                for (int j = 0; j < 8; ++j)
                    acc[i][j] = fmaf(qv[i], ev[j], acc[i][j]);
        }
        __syncthreads();
    }

    // Write back (float4 x2 per row)
#pragma unroll
    for (int i = 0; i < 8; ++i) {
        float* dst = g_scores + ((size_t)b * SEQ_ + mBase + ty * 8 + i) * V_
                     + vBase + tx * 8;
        float4 o0 = make_float4(acc[i][0], acc[i][1], acc[i][2], acc[i][3]);
        float4 o1 = make_float4(acc[i][4], acc[i][5], acc[i][6], acc[i][7]);
        *(float4*)dst = o0;
        *(float4*)(dst + 4) = o1;
    }
}

// ---------------------------------------------------------------------------
// Gather: out[p][i][j] = scores[b, rb*32 + i, info[p][i][j]]
// One CTA = CHUNK consecutive panels. Panels sharing (b, rb) are contiguous in
// p (tril_indices order), so the 32 needed score rows (64 KB) are staged in
// dynamic smem once per run. Each thread handles 4 contiguous elements per
// panel (int4 -> 4x LDS -> float4), with the next panel's indices prefetched
// to keep memory-level parallelism up.
// ---------------------------------------------------------------------------
__global__ __launch_bounds__(256) void gather_kernel(
    const int* __restrict__ info,
    const int* __restrict__ idxs_batch,
    const int* __restrict__ idxs_row,
    float* __restrict__ out,
    int P) {
    extern __shared__ float s[];   // 64 KB: 32 score rows x 512 floats

    const int p0 = blockIdx.x * CHUNK;
    if (p0 >= P) return;
    const int pend = min(p0 + CHUNK, P);
    const int tid = threadIdx.x;
    const float* srow = s + (tid >> 3) * V_;   // i_local = tid*4/32

    int cached = -1;
    // prefetch first panel's indices
    int4 idx = ((const int4*)(info + (size_t)p0 * 1024))[tid];

    for (int p = p0; p < pend; ++p) {
        // prefetch next panel's indices early (independent of smem state)
        int4 idx_next;
        if (p + 1 < pend)
            idx_next = ((const int4*)(info + (size_t)(p + 1) * 1024))[tid];

        const int b  = __ldg(&idxs_batch[p]);
        const int rb = __ldg(&idxs_row[p]);
        const int key = (b << 8) | rb;
        if (key != cached) {
            __syncthreads();   // previous panel's gathers done
            const float4* __restrict__ src = (const float4*)(
                g_scores + ((size_t)b * SEQ_ + rb * BS_) * V_);
            float4* dst = (float4*)s;
#pragma unroll
            for (int t = 0; t < 16; ++t)
                dst[tid + t * 256] = src[tid + t * 256];
            cached = key;
            __syncthreads();
        }

        float4 o;
        o.x = srow[idx.x];
        o.y = srow[idx.y];
        o.z = srow[idx.z];
        o.w = srow[idx.w];
        ((float4*)(out + (size_t)p * 1024))[tid] = o;

        idx = idx_next;
    }
}

// ---------------------------------------------------------------------------
extern "C" void kernel_launch(void* const* d_in, const int* in_sizes, int n_in,
                              void* d_out, int out_size) {
    const float* q    = (const float*)d_in[0];
    const float* emb  = (const float*)d_in[1];
    const int*   info = (const int*)d_in[2];
    const int*   idxb = (const int*)d_in[3];
    const int*   idxr = (const int*)d_in[4];
    float* out = (float*)d_out;
    const int P = in_sizes[3];

    static int smem_set = 0;
    if (!smem_set) {
        cudaFuncSetAttribute(gather_kernel,
                             cudaFuncAttributeMaxDynamicSharedMemorySize,
                             BS_ * V_ * sizeof(float));
        smem_set = 1;
    }

    dim3 tb(32, 8);
    transpose_q_kernel<<<dim3(D_ / 32, SEQ_ / 32, B_), tb>>>(q);
    transpose_e_kernel<<<dim3(D_ / 32, V_ / 32, B_), tb>>>(emb);

    gemm_kernel<<<dim3(SEQ_ / 128, V_ / 128, B_), 256>>>();

    gather_kernel<<<(P + CHUNK - 1) / CHUNK, 256,
                    BS_ * V_ * sizeof(float)>>>(info, idxb, idxr, out, P);
}

// round 3
// speedup vs baseline: 1.3265x; 1.1990x over previous
#include <cuda_runtime.h>
#include <cuda_bf16.h>

#define B_    4
#define SEQ_  4096
#define D_    64
#define V_    512
#define BS_   32
#define R_    128          // SEQ/BS
#define PPB_  8256         // panels per batch = R(R+1)/2
#define CHUNK 32           // max panels per gather CTA (run-aligned)

// Scratch (device globals — no allocation allowed)
__device__ float g_qT[(size_t)B_ * D_ * SEQ_];            // [b][d][m]
__device__ float g_eT[(size_t)B_ * D_ * V_];              // [b][d][v]
__device__ float g_scores[(size_t)B_ * SEQ_ * V_];        // [b][m][v]

// ---------------------------------------------------------------------------
// Transpose [R][C] -> [C][R] per batch (32x32 smem tiles), all dims %32 == 0
// ---------------------------------------------------------------------------
__device__ __forceinline__ void transpose_body(const float* __restrict__ in,
                                               float* __restrict__ out,
                                               int R, int C) {
    __shared__ float tile[32][33];
    const float* inb = in + (size_t)blockIdx.z * R * C;
    float* outb = out + (size_t)blockIdx.z * R * C;
    int c0 = blockIdx.x * 32;
    int r0 = blockIdx.y * 32;
#pragma unroll
    for (int dy = 0; dy < 32; dy += 8)
        tile[threadIdx.y + dy][threadIdx.x] =
            inb[(size_t)(r0 + threadIdx.y + dy) * C + c0 + threadIdx.x];
    __syncthreads();
#pragma unroll
    for (int dy = 0; dy < 32; dy += 8)
        outb[(size_t)(c0 + threadIdx.y + dy) * R + r0 + threadIdx.x] =
            tile[threadIdx.x][threadIdx.y + dy];
}

__global__ void transpose_q_kernel(const float* __restrict__ q) {
    transpose_body(q, g_qT, SEQ_, D_);
}
__global__ void transpose_e_kernel(const float* __restrict__ emb) {
    transpose_body(emb, g_eT, V_, D_);
}

// ---------------------------------------------------------------------------
// GEMM: scores[b][m][v] = sum_k qT[b][k][m] * eT[b][k][v]
// CTA tile 128(M) x 128(V), K staged in two 32-deep smem phases (32 KB smem).
// 256 threads, 8x8 micro-tile per thread.
// ---------------------------------------------------------------------------
__global__ __launch_bounds__(256) void gemm_kernel() {
    __shared__ float qs[32][128];
    __shared__ float es[32][128];

    const int b = blockIdx.z;
    const int mBase = blockIdx.x * 128;
    const int vBase = blockIdx.y * 128;
    const int tid = threadIdx.x;
    const int tx = tid & 15;   // v direction (16)
    const int ty = tid >> 4;   // m direction (16)

    const float* __restrict__ qTb = g_qT + (size_t)b * D_ * SEQ_;
    const float* __restrict__ eTb = g_eT + (size_t)b * D_ * V_;

    float acc[8][8];
#pragma unroll
    for (int i = 0; i < 8; ++i)
#pragma unroll
        for (int j = 0; j < 8; ++j) acc[i][j] = 0.0f;

    const int f  = tid & 31;   // float4 column within 128-wide tile row
    const int kr = tid >> 5;   // 0..7

#pragma unroll
    for (int kp = 0; kp < 2; ++kp) {
#pragma unroll
        for (int t = 0; t < 4; ++t) {
            int k = kr + t * 8;
            *(float4*)&qs[k][f * 4] =
                *(const float4*)&qTb[(size_t)(kp * 32 + k) * SEQ_ + mBase + f * 4];
            *(float4*)&es[k][f * 4] =
                *(const float4*)&eTb[(size_t)(kp * 32 + k) * V_ + vBase + f * 4];
        }
        __syncthreads();

#pragma unroll 8
        for (int k = 0; k < 32; ++k) {
            float qv[8], ev[8];
            *(float4*)&qv[0] = *(const float4*)&qs[k][ty * 8];
            *(float4*)&qv[4] = *(const float4*)&qs[k][ty * 8 + 4];
            *(float4*)&ev[0] = *(const float4*)&es[k][tx * 8];
            *(float4*)&ev[4] = *(const float4*)&es[k][tx * 8 + 4];
#pragma unroll
            for (int i = 0; i < 8; ++i)
#pragma unroll
                for (int j = 0; j < 8; ++j)
                    acc[i][j] = fmaf(qv[i], ev[j], acc[i][j]);
        }
        __syncthreads();
    }

#pragma unroll
    for (int i = 0; i < 8; ++i) {
        float* dst = g_scores + ((size_t)b * SEQ_ + mBase + ty * 8 + i) * V_
                     + vBase + tx * 8;
        *(float4*)dst = make_float4(acc[i][0], acc[i][1], acc[i][2], acc[i][3]);
        *(float4*)(dst + 4) = make_float4(acc[i][4], acc[i][5], acc[i][6], acc[i][7]);
    }
}

// ---------------------------------------------------------------------------
// Run-aligned gather. tril_indices structure: for batch b, row-block rb, there
// are rb+1 consecutive panels. Each CTA owns <=32 panels of ONE run, so the 32
// score rows are staged exactly once, and the hot loop has no syncs/branches.
// Per-batch chunk count: rb in [32g, 32g+31] contributes g+1 chunks each ->
// 320 chunks/batch. 512 threads: 2 panels per iteration, 4 elems per thread.
// ---------------------------------------------------------------------------
__global__ __launch_bounds__(512) void gather_run_kernel(
    const int* __restrict__ info,
    const int* __restrict__ idxs_batch,
    const int* __restrict__ idxs_row,
    float* __restrict__ out) {
    extern __shared__ float s[];   // 64 KB: 32 rows x 512 floats

    // Decode (b, rb, chunk) from blockIdx.x
    const int x  = blockIdx.x;
    const int bi = x / 320;
    const int xb = x - bi * 320;
    int g, base;
    if (xb < 32)       { g = 0; base = 0;   }
    else if (xb < 96)  { g = 1; base = 32;  }
    else if (xb < 192) { g = 2; base = 96;  }
    else               { g = 3; base = 192; }
    const int rb_idx = (g << 5) + (xb - base) / (g + 1);
    const int c      = (xb - base) % (g + 1);
    const int p_start = bi * PPB_ + (rb_idx * (rb_idx + 1)) / 2 + c * CHUNK;
    const int count   = min(CHUNK, rb_idx + 1 - c * CHUNK);

    // Values of b/rb read from the actual inputs (one scalar load per CTA)
    const int b  = __ldg(&idxs_batch[p_start]);
    const int rb = __ldg(&idxs_row[p_start]);

    const int tid = threadIdx.x;
    const int sub = tid >> 8;      // which of the 2 panels this iteration
    const int t   = tid & 255;     // position within panel (4 elems)
    const float* srow = s + (t >> 3) * V_;

    // Prefetch first index vector while staging
    int4 idx;
    if (sub < count)
        idx = ((const int4*)info)[(size_t)(p_start + sub) * 256 + t];

    // Stage the 32 score rows (64 KB), 8 float4 per thread
    {
        const float4* __restrict__ src = (const float4*)(
            g_scores + ((size_t)b * SEQ_ + rb * BS_) * V_);
        float4* dst = (float4*)s;
#pragma unroll
        for (int i = 0; i < 8; ++i)
            dst[tid + i * 512] = src[tid + i * 512];
    }
    __syncthreads();

    for (int pp = 0; pp < count; pp += 2) {
        const int pcur = pp + sub;
        const int pnext = pcur + 2;
        int4 idxn;
        if (pnext < count)
            idxn = ((const int4*)info)[(size_t)(p_start + pnext) * 256 + t];

        if (pcur < count) {
            float4 o;
            o.x = srow[idx.x];
            o.y = srow[idx.y];
            o.z = srow[idx.z];
            o.w = srow[idx.w];
            ((float4*)out)[(size_t)(p_start + pcur) * 256 + t] = o;
        }
        idx = idxn;
    }
}

// ---------------------------------------------------------------------------
// Generic fallback gather (any P / structure): round-2 version.
// ---------------------------------------------------------------------------
__global__ __launch_bounds__(256) void gather_fallback_kernel(
    const int* __restrict__ info,
    const int* __restrict__ idxs_batch,
    const int* __restrict__ idxs_row,
    float* __restrict__ out,
    int P) {
    extern __shared__ float s[];
    const int p0 = blockIdx.x * 16;
    if (p0 >= P) return;
    const int pend = min(p0 + 16, P);
    const int tid = threadIdx.x;
    const float* srow = s + (tid >> 3) * V_;

    int cached = -1;
    int4 idx = ((const int4*)(info + (size_t)p0 * 1024))[tid];
    for (int p = p0; p < pend; ++p) {
        int4 idx_next;
        if (p + 1 < pend)
            idx_next = ((const int4*)(info + (size_t)(p + 1) * 1024))[tid];
        const int b  = __ldg(&idxs_batch[p]);
        const int rb = __ldg(&idxs_row[p]);
        const int key = (b << 16) | rb;
        if (key != cached) {
            __syncthreads();
            const float4* __restrict__ src = (const float4*)(
                g_scores + ((size_t)b * SEQ_ + rb * BS_) * V_);
            float4* dst = (float4*)s;
#pragma unroll
            for (int t2 = 0; t2 < 16; ++t2)
                dst[tid + t2 * 256] = src[tid + t2 * 256];
            cached = key;
            __syncthreads();
        }
        float4 o;
        o.x = srow[idx.x];
        o.y = srow[idx.y];
        o.z = srow[idx.z];
        o.w = srow[idx.w];
        ((float4*)(out + (size_t)p * 1024))[tid] = o;
        idx = idx_next;
    }
}

// ---------------------------------------------------------------------------
extern "C" void kernel_launch(void* const* d_in, const int* in_sizes, int n_in,
                              void* d_out, int out_size) {
    const float* q    = (const float*)d_in[0];
    const float* emb  = (const float*)d_in[1];
    const int*   info = (const int*)d_in[2];
    const int*   idxb = (const int*)d_in[3];
    const int*   idxr = (const int*)d_in[4];
    float* out = (float*)d_out;
    const int P = in_sizes[3];

    static int smem_set = 0;
    if (!smem_set) {
        cudaFuncSetAttribute(gather_run_kernel,
                             cudaFuncAttributeMaxDynamicSharedMemorySize,
                             BS_ * V_ * sizeof(float));
        cudaFuncSetAttribute(gather_fallback_kernel,
                             cudaFuncAttributeMaxDynamicSharedMemorySize,
                             BS_ * V_ * sizeof(float));
        smem_set = 1;
    }

    dim3 tb(32, 8);
    transpose_q_kernel<<<dim3(D_ / 32, SEQ_ / 32, B_), tb>>>(q);
    transpose_e_kernel<<<dim3(D_ / 32, V_ / 32, B_), tb>>>(emb);

    gemm_kernel<<<dim3(SEQ_ / 128, V_ / 128, B_), 256>>>();

    if (P == B_ * PPB_) {
        gather_run_kernel<<<B_ * 320, 512, BS_ * V_ * sizeof(float)>>>(
            info, idxb, idxr, out);
    } else {
        gather_fallback_kernel<<<(P + 15) / 16, 256, BS_ * V_ * sizeof(float)>>>(
            info, idxb, idxr, out, P);
    }
}

// round 4
// speedup vs baseline: 1.4295x; 1.0777x over previous
#include <cuda_runtime.h>
#include <cuda_bf16.h>

#define B_    4
#define SEQ_  4096
#define D_    64
#define V_    512
#define BS_   32
#define R_    128          // SEQ/BS
#define PPB_  8256         // panels per batch = R(R+1)/2
#define CHUNK 32           // max panels per gather CTA (run-aligned)

typedef unsigned long long u64;

// Scratch (device globals — no allocation allowed)
__device__ float g_qT[(size_t)B_ * D_ * SEQ_];            // [b][d][m]
__device__ float g_eT[(size_t)B_ * D_ * V_];              // [b][d][v]
__device__ float g_scores[(size_t)B_ * SEQ_ * V_];        // [b][m][v]

#define FMA_F32X2(d, a, b, c) \
    asm("fma.rn.f32x2 %0, %1, %2, %3;" : "=l"(d) : "l"(a), "l"(b), "l"(c))
#define PACK_F32X2(out, lo, hi) \
    asm("mov.b64 %0, {%1, %2};" : "=l"(out) : "f"(lo), "f"(hi))
#define UNPACK_F32X2(lo, hi, in) \
    asm("mov.b64 {%0, %1}, %2;" : "=f"(lo), "=f"(hi) : "l"(in))

// ---------------------------------------------------------------------------
// Fused transpose: q [SEQ][D] -> g_qT [D][SEQ] and emb [V][D] -> g_eT [D][V]
// 32x32 smem tiles; blockIdx.y selects which tensor.
// ---------------------------------------------------------------------------
__global__ void transpose_kernel(const float* __restrict__ q,
                                 const float* __restrict__ emb) {
    __shared__ float tile[32][33];
    const float* in;
    float* out;
    int R, C, r0;
    if (blockIdx.y < SEQ_ / 32) {
        in = q;  out = g_qT;  R = SEQ_;  C = D_;  r0 = blockIdx.y * 32;
    } else {
        in = emb; out = g_eT; R = V_;    C = D_;  r0 = (blockIdx.y - SEQ_ / 32) * 32;
    }
    const float* inb = in + (size_t)blockIdx.z * R * C;
    float* outb = out + (size_t)blockIdx.z * R * C;
    int c0 = blockIdx.x * 32;
#pragma unroll
    for (int dy = 0; dy < 32; dy += 8)
        tile[threadIdx.y + dy][threadIdx.x] =
            inb[(size_t)(r0 + threadIdx.y + dy) * C + c0 + threadIdx.x];
    __syncthreads();
#pragma unroll
    for (int dy = 0; dy < 32; dy += 8)
        outb[(size_t)(c0 + threadIdx.y + dy) * R + r0 + threadIdx.x] =
            tile[threadIdx.x][threadIdx.y + dy];
}

// ---------------------------------------------------------------------------
// GEMM: scores[b][m][v] = sum_k qT[b][k][m] * eT[b][k][v]
// CTA tile 128(M) x 128(V), K in two 32-deep smem phases. 256 threads,
// 8x8 micro-tile per thread, inner product via packed fma.rn.f32x2
// (2 FMAs/instr on the fp32 pipe — PTX-only on sm_103a).
// ---------------------------------------------------------------------------
__global__ __launch_bounds__(256) void gemm_kernel() {
    __shared__ float qs[32][128];
    __shared__ float es[32][128];

    const int b = blockIdx.z;
    const int mBase = blockIdx.x * 128;
    const int vBase = blockIdx.y * 128;
    const int tid = threadIdx.x;
    const int tx = tid & 15;   // v direction (16)
    const int ty = tid >> 4;   // m direction (16)

    const float* __restrict__ qTb = g_qT + (size_t)b * D_ * SEQ_;
    const float* __restrict__ eTb = g_eT + (size_t)b * D_ * V_;

    u64 acc2[8][4];
#pragma unroll
    for (int i = 0; i < 8; ++i)
#pragma unroll
        for (int j = 0; j < 4; ++j) acc2[i][j] = 0ull;

    const int f  = tid & 31;   // float4 column within 128-wide tile row
    const int kr = tid >> 5;   // 0..7

#pragma unroll
    for (int kp = 0; kp < 2; ++kp) {
#pragma unroll
        for (int t = 0; t < 4; ++t) {
            int k = kr + t * 8;
            *(float4*)&qs[k][f * 4] =
                *(const float4*)&qTb[(size_t)(kp * 32 + k) * SEQ_ + mBase + f * 4];
            *(float4*)&es[k][f * 4] =
                *(const float4*)&eTb[(size_t)(kp * 32 + k) * V_ + vBase + f * 4];
        }
        __syncthreads();

#pragma unroll 8
        for (int k = 0; k < 32; ++k) {
            float qv[8], ev[8];
            *(float4*)&qv[0] = *(const float4*)&qs[k][ty * 8];
            *(float4*)&qv[4] = *(const float4*)&qs[k][ty * 8 + 4];
            *(float4*)&ev[0] = *(const float4*)&es[k][tx * 8];
            *(float4*)&ev[4] = *(const float4*)&es[k][tx * 8 + 4];

            u64 qd[8], ed[4];
#pragma unroll
            for (int i = 0; i < 8; ++i) PACK_F32X2(qd[i], qv[i], qv[i]);
#pragma unroll
            for (int j = 0; j < 4; ++j) PACK_F32X2(ed[j], ev[2 * j], ev[2 * j + 1]);
#pragma unroll
            for (int i = 0; i < 8; ++i)
#pragma unroll
                for (int j = 0; j < 4; ++j)
                    FMA_F32X2(acc2[i][j], qd[i], ed[j], acc2[i][j]);
        }
        __syncthreads();
    }

#pragma unroll
    for (int i = 0; i < 8; ++i) {
        float o[8];
#pragma unroll
        for (int j = 0; j < 4; ++j) UNPACK_F32X2(o[2 * j], o[2 * j + 1], acc2[i][j]);
        float* dst = g_scores + ((size_t)b * SEQ_ + mBase + ty * 8 + i) * V_
                     + vBase + tx * 8;
        *(float4*)dst = make_float4(o[0], o[1], o[2], o[3]);
        *(float4*)(dst + 4) = make_float4(o[4], o[5], o[6], o[7]);
    }
}

// ---------------------------------------------------------------------------
// Run-aligned gather. For batch b, row-block rb there are rb+1 consecutive
// panels; each CTA owns <=32 panels of ONE run, staging the 32 score rows
// (64 KB) exactly once. 1024 threads: 4 panels per iteration, 4 elems/thread.
// ---------------------------------------------------------------------------
__global__ __launch_bounds__(1024) void gather_run_kernel(
    const int* __restrict__ info,
    const int* __restrict__ idxs_batch,
    const int* __restrict__ idxs_row,
    float* __restrict__ out) {
    extern __shared__ float s[];   // 64 KB: 32 rows x 512 floats

    // Decode (b, rb, chunk) from blockIdx.x
    const int x  = blockIdx.x;
    const int bi = x / 320;
    const int xb = x - bi * 320;
    int g, base;
    if (xb < 32)       { g = 0; base = 0;   }
    else if (xb < 96)  { g = 1; base = 32;  }
    else if (xb < 192) { g = 2; base = 96;  }
    else               { g = 3; base = 192; }
    const int rb_idx = (g << 5) + (xb - base) / (g + 1);
    const int c      = (xb - base) % (g + 1);
    const int p_start = bi * PPB_ + (rb_idx * (rb_idx + 1)) / 2 + c * CHUNK;
    const int count   = min(CHUNK, rb_idx + 1 - c * CHUNK);

    // Values of b/rb read from the actual inputs (one scalar load per CTA)
    const int b  = __ldg(&idxs_batch[p_start]);
    const int rb = __ldg(&idxs_row[p_start]);

    const int tid = threadIdx.x;
    const int sub = tid >> 8;      // which of 4 panels this iteration (0..3)
    const int t   = tid & 255;     // position within panel (4 elems)
    const float* srow = s + (t >> 3) * V_;

    // Prefetch first index vector while staging
    int4 idx;
    if (sub < count)
        idx = ((const int4*)info)[(size_t)(p_start + sub) * 256 + t];

    // Stage the 32 score rows (64 KB), 4 float4 per thread
    {
        const float4* __restrict__ src = (const float4*)(
            g_scores + ((size_t)b * SEQ_ + rb * BS_) * V_);
        float4* dst = (float4*)s;
#pragma unroll
        for (int i = 0; i < 4; ++i)
            dst[tid + i * 1024] = src[tid + i * 1024];
    }
    __syncthreads();

    for (int pp = 0; pp < count; pp += 4) {
        const int pcur = pp + sub;
        const int pnext = pcur + 4;
        int4 idxn;
        if (pnext < count)
            idxn = ((const int4*)info)[(size_t)(p_start + pnext) * 256 + t];

        if (pcur < count) {
            float4 o;
            o.x = srow[idx.x];
            o.y = srow[idx.y];
            o.z = srow[idx.z];
            o.w = srow[idx.w];
            ((float4*)out)[(size_t)(p_start + pcur) * 256 + t] = o;
        }
        idx = idxn;
    }
}

// ---------------------------------------------------------------------------
// Generic fallback gather (any P / structure).
// ---------------------------------------------------------------------------
__global__ __launch_bounds__(256) void gather_fallback_kernel(
    const int* __restrict__ info,
    const int* __restrict__ idxs_batch,
    const int* __restrict__ idxs_row,
    float* __restrict__ out,
    int P) {
    extern __shared__ float s[];
    const int p0 = blockIdx.x * 16;
    if (p0 >= P) return;
    const int pend = min(p0 + 16, P);
    const int tid = threadIdx.x;
    const float* srow = s + (tid >> 3) * V_;

    int cached = -1;
    int4 idx = ((const int4*)(info + (size_t)p0 * 1024))[tid];
    for (int p = p0; p < pend; ++p) {
        int4 idx_next;
        if (p + 1 < pend)
            idx_next = ((const int4*)(info + (size_t)(p + 1) * 1024))[tid];
        const int b  = __ldg(&idxs_batch[p]);
        const int rb = __ldg(&idxs_row[p]);
        const int key = (b << 16) | rb;
        if (key != cached) {
            __syncthreads();
            const float4* __restrict__ src = (const float4*)(
                g_scores + ((size_t)b * SEQ_ + rb * BS_) * V_);
            float4* dst = (float4*)s;
#pragma unroll
            for (int t2 = 0; t2 < 16; ++t2)
                dst[tid + t2 * 256] = src[tid + t2 * 256];
            cached = key;
            __syncthreads();
        }
        float4 o;
        o.x = srow[idx.x];
        o.y = srow[idx.y];
        o.z = srow[idx.z];
        o.w = srow[idx.w];
        ((float4*)(out + (size_t)p * 1024))[tid] = o;
        idx = idx_next;
    }
}

// ---------------------------------------------------------------------------
extern "C" void kernel_launch(void* const* d_in, const int* in_sizes, int n_in,
                              void* d_out, int out_size) {
    const float* q    = (const float*)d_in[0];
    const float* emb  = (const float*)d_in[1];
    const int*   info = (const int*)d_in[2];
    const int*   idxb = (const int*)d_in[3];
    const int*   idxr = (const int*)d_in[4];
    float* out = (float*)d_out;
    const int P = in_sizes[3];

    static int smem_set = 0;
    if (!smem_set) {
        cudaFuncSetAttribute(gather_run_kernel,
                             cudaFuncAttributeMaxDynamicSharedMemorySize,
                             BS_ * V_ * sizeof(float));
        cudaFuncSetAttribute(gather_fallback_kernel,
                             cudaFuncAttributeMaxDynamicSharedMemorySize,
                             BS_ * V_ * sizeof(float));
        smem_set = 1;
    }

    dim3 tb(32, 8);
    transpose_kernel<<<dim3(D_ / 32, SEQ_ / 32 + V_ / 32, B_), tb>>>(q, emb);

    gemm_kernel<<<dim3(SEQ_ / 128, V_ / 128, B_), 256>>>();

    if (P == B_ * PPB_) {
        gather_run_kernel<<<B_ * 320, 1024, BS_ * V_ * sizeof(float)>>>(
            info, idxb, idxr, out);
    } else {
        gather_fallback_kernel<<<(P + 15) / 16, 256, BS_ * V_ * sizeof(float)>>>(
            info, idxb, idxr, out, P);
    }
}